// round 14
// baseline (speedup 1.0000x reference)
#include <cuda_runtime.h>
#include <cuda_fp16.h>
#include <math.h>
#include <stdint.h>

#define BATCH 32
#define SQ 512
#define SK 512
#define DIM 512
#define DIM2 1024
#define SCALE 0.044194173824159216f  // 1/sqrt(512)

// CTA 128x128, 4 warps of 64x64, BK=64 fp16, 3-stage cp.async ring (wait<=1).
// A / NT-B smem rows: 128B (64 fp16), XOR swizzle chunk^=(row&7).
// ctx-B smem rows: 256B (128 fp16, k-major), XOR swizzle chunk^=(krow&7).
#define BK 64
#define STG_OP (128 * 128)         // 16384 B per operand stage
#define STG_PAIR (2 * STG_OP)      // 32768
#define SMEM_NT (3 * STG_PAIR)     // 98304 (opt-in; 2 CTAs/SM = 192KB <= 228KB)

// fp16 operand buffers
__device__ uint2 g_Qh[BATCH * SQ * DIM / 4];
__device__ uint2 g_Eh[BATCH * SK * DIM / 4];
__device__ uint2 g_Wh[DIM * DIM2 / 4];
__device__ uint2 g_Ah[BATCH * SQ * SK / 4];
__device__ uint2 g_Ch[BATCH * SQ * DIM / 4];

__device__ __forceinline__ uint32_t f2h2(float lo, float hi) {
    uint32_t r;
    asm("cvt.rn.f16x2.f32 %0, %1, %2;" : "=r"(r) : "f"(hi), "f"(lo));
    return r;
}
__device__ __forceinline__ void cp16(uint32_t smem_dst, const void* gsrc) {
    asm volatile("cp.async.cg.shared.global [%0], [%1], 16;" :: "r"(smem_dst), "l"(gsrc));
}
__device__ __forceinline__ void cp_commit() { asm volatile("cp.async.commit_group;"); }
template <int N>
__device__ __forceinline__ void cp_wait() { asm volatile("cp.async.wait_group %0;" :: "n"(N)); }
__device__ __forceinline__ uint32_t smem_u32(const void* p) {
    uint32_t a;
    asm("{ .reg .u64 t; cvta.to.shared.u64 t, %1; cvt.u32.u64 %0, t; }" : "=r"(a) : "l"(p));
    return a;
}
__device__ __forceinline__ void ldsm4(uint32_t& r0, uint32_t& r1, uint32_t& r2, uint32_t& r3,
                                      uint32_t a) {
    asm volatile("ldmatrix.sync.aligned.m8n8.x4.shared.b16 {%0,%1,%2,%3}, [%4];"
                 : "=r"(r0), "=r"(r1), "=r"(r2), "=r"(r3) : "r"(a));
}
__device__ __forceinline__ void ldsm4t(uint32_t& r0, uint32_t& r1, uint32_t& r2, uint32_t& r3,
                                       uint32_t a) {
    asm volatile("ldmatrix.sync.aligned.m8n8.x4.trans.shared.b16 {%0,%1,%2,%3}, [%4];"
                 : "=r"(r0), "=r"(r1), "=r"(r2), "=r"(r3) : "r"(a));
}
__device__ __forceinline__ void mma_f16(float c[4], const uint32_t a[4],
                                        uint32_t b0, uint32_t b1) {
    asm volatile(
        "mma.sync.aligned.m16n8k16.row.col.f32.f16.f16.f32 "
        "{%0,%1,%2,%3}, {%4,%5,%6,%7}, {%8,%9}, {%0,%1,%2,%3};"
        : "+f"(c[0]), "+f"(c[1]), "+f"(c[2]), "+f"(c[3])
        : "r"(a[0]), "r"(a[1]), "r"(a[2]), "r"(a[3]), "r"(b0), "r"(b1));
}

// NT compute on one BK=64 stage: both operands [row][k], 128B rows
__device__ __forceinline__ void compute_fp16(
    uint32_t abase, uint32_t bbase, int m0, int n0, int lane, float acc[4][8][4])
{
    const int q = lane >> 3;
    const int arof = (q & 1) * 8 + (lane & 7);
    const int acq = q >> 1;
    const int brof = (q >> 1) * 8 + (lane & 7);
    const int bcq = q & 1;
    #pragma unroll
    for (int kh = 0; kh < 4; kh++) {             // k = 0,16,32,48 -> chunk base 0,2,4,6
        const int cb = kh * 2;
        uint32_t a[4][4];
        #pragma unroll
        for (int mi = 0; mi < 4; mi++) {
            int row = m0 + mi * 16 + arof;
            uint32_t ad = abase + row * 128 + (((cb + acq) ^ (row & 7)) << 4);
            ldsm4(a[mi][0], a[mi][1], a[mi][2], a[mi][3], ad);
        }
        #pragma unroll
        for (int njp = 0; njp < 4; njp++) {
            int row = n0 + njp * 16 + brof;
            uint32_t bd = bbase + row * 128 + (((cb + bcq) ^ (row & 7)) << 4);
            uint32_t b0, b1, b2, b3;
            ldsm4(b0, b1, b2, b3, bd);
            #pragma unroll
            for (int mi = 0; mi < 4; mi++) {
                mma_f16(acc[mi][njp * 2], a[mi], b0, b1);
                mma_f16(acc[mi][njp * 2 + 1], a[mi], b2, b3);
            }
        }
    }
}

// ctx compute: A [q][k] 128B rows, B [k][d] 256B rows via ldmatrix.trans
__device__ __forceinline__ void compute_ctx(
    uint32_t abase, uint32_t bbase, int m0, int n0, int lane, float acc[4][8][4])
{
    const int q = lane >> 3;
    const int l = lane & 7;
    const int arof = (q & 1) * 8 + l;
    const int acq = q >> 1;
    const int bko = (q & 1) * 8 + l;   // k-row within 16-half
    const int bcq = q >> 1;            // d-group +0 / +1
    #pragma unroll
    for (int kh = 0; kh < 4; kh++) {
        const int cb = kh * 2;
        uint32_t a[4][4];
        #pragma unroll
        for (int mi = 0; mi < 4; mi++) {
            int row = m0 + mi * 16 + arof;
            uint32_t ad = abase + row * 128 + (((cb + acq) ^ (row & 7)) << 4);
            ldsm4(a[mi][0], a[mi][1], a[mi][2], a[mi][3], ad);
        }
        #pragma unroll
        for (int njp = 0; njp < 4; njp++) {
            int krow = kh * 16 + bko;                // 0..63
            int chunk = (n0 >> 3) + njp * 2 + bcq;   // d-chunk (16B)
            uint32_t bd = bbase + krow * 256 + ((chunk ^ (krow & 7)) << 4);
            uint32_t b0, b1, b2, b3;
            ldsm4t(b0, b1, b2, b3, bd);
            #pragma unroll
            for (int mi = 0; mi < 4; mi++) {
                mma_f16(acc[mi][njp * 2], a[mi], b0, b1);
                mma_f16(acc[mi][njp * 2 + 1], a[mi], b2, b3);
            }
        }
    }
}

// ---------------------------------------------------------------------------
// Kernel 1: raw scores = Qh . Eh^T  (NT, K=512); SCALE applied in softmax
// ---------------------------------------------------------------------------
__global__ __launch_bounds__(128, 2) void hgemm_scores(
    const __half* __restrict__ Qh, const __half* __restrict__ Eh,
    float* __restrict__ S)
{
    extern __shared__ uint32_t sm[];
    const int b = blockIdx.z, mBase = blockIdx.y * 128, nBase = blockIdx.x * 128;
    const __half* Ab = Qh + (size_t)b * SQ * DIM + (size_t)mBase * DIM;
    const __half* Bb = Eh + (size_t)b * SK * DIM + (size_t)nBase * DIM;
    float* Sb = S + (size_t)b * SQ * SK;

    const int tid = threadIdx.x, lane = tid & 31, w = tid >> 5;
    const int m0 = (w & 1) * 64, n0 = (w >> 1) * 64;
    const int lc = tid & 7, lr = tid >> 3;   // loader: chunk 0-7, row 0-15 (+16i)
    const uint32_t sbase = smem_u32(sm);

    float acc[4][8][4];
    #pragma unroll
    for (int i = 0; i < 4; i++)
        #pragma unroll
        for (int j = 0; j < 8; j++)
            #pragma unroll
            for (int qq = 0; qq < 4; qq++) acc[i][j][qq] = 0.f;

    auto issue = [&](int p) {
        uint32_t st = sbase + (p % 3) * STG_PAIR;
        int k = p * BK;
        #pragma unroll
        for (int i = 0; i < 8; i++) {
            int row = lr + 16 * i;
            uint32_t sw = (uint32_t)(row * 128 + ((lc ^ (row & 7)) << 4));
            cp16(st + sw, Ab + (size_t)row * DIM + k + lc * 8);
            cp16(st + STG_OP + sw, Bb + (size_t)row * DIM + k + lc * 8);
        }
        cp_commit();
    };

    issue(0); issue(1);
    const int NP = 8;
    for (int p = 0; p < NP; p++) {
        if (p + 1 < NP) cp_wait<1>(); else cp_wait<0>();
        __syncthreads();
        if (p + 2 < NP) issue(p + 2);
        uint32_t ab = sbase + (p % 3) * STG_PAIR;
        compute_fp16(ab, ab + STG_OP, m0, n0, lane, acc);
    }

    #pragma unroll
    for (int mi = 0; mi < 4; mi++)
        #pragma unroll
        for (int nj = 0; nj < 8; nj++) {
            int row = mBase + m0 + mi * 16 + (lane >> 2);
            int col = nBase + n0 + nj * 8 + (lane & 3) * 2;
            *(float2*)(Sb + (size_t)row * SK + col) =
                make_float2(acc[mi][nj][0], acc[mi][nj][1]);
            *(float2*)(Sb + (size_t)(row + 8) * SK + col) =
                make_float2(acc[mi][nj][2], acc[mi][nj][3]);
        }
}

// ---------------------------------------------------------------------------
// Kernel 3: ctx = Ah . Eh  (A NT, B trans-ldmatrix on [k][d], K=512) -> fp16
// ---------------------------------------------------------------------------
__global__ __launch_bounds__(128, 2) void hgemm_ctx(
    const __half* __restrict__ Ah, const __half* __restrict__ Eh,
    __half* __restrict__ Ch)
{
    extern __shared__ uint32_t sm[];
    const int b = blockIdx.z, mBase = blockIdx.y * 128, nBase = blockIdx.x * 128;
    const __half* Ab = Ah + (size_t)b * SQ * SK + (size_t)mBase * SK;
    const __half* Bb = Eh + (size_t)b * SK * DIM + nBase;   // [k][d] slab
    __half* Cb = Ch + (size_t)b * SQ * DIM;

    const int tid = threadIdx.x, lane = tid & 31, w = tid >> 5;
    const int m0 = (w & 1) * 64, n0 = (w >> 1) * 64;
    const int lc = tid & 7, lr = tid >> 3;       // A loader
    const int bkr = tid >> 1, bcb = tid & 1;     // B loader: k-row 0..63, chunk parity
    const uint32_t sbase = smem_u32(sm);

    float acc[4][8][4];
    #pragma unroll
    for (int i = 0; i < 4; i++)
        #pragma unroll
        for (int j = 0; j < 8; j++)
            #pragma unroll
            for (int qq = 0; qq < 4; qq++) acc[i][j][qq] = 0.f;

    auto issue = [&](int p) {
        uint32_t st = sbase + (p % 3) * STG_PAIR;
        int k = p * BK;
        #pragma unroll
        for (int i = 0; i < 8; i++) {
            int row = lr + 16 * i;
            uint32_t sw = (uint32_t)(row * 128 + ((lc ^ (row & 7)) << 4));
            cp16(st + sw, Ab + (size_t)row * SK + k + lc * 8);
        }
        #pragma unroll
        for (int j = 0; j < 8; j++) {
            int chunk = bcb + j * 2;    // 0..15 (d-chunk of 8 fp16)
            uint32_t sw = (uint32_t)(bkr * 256 + ((chunk ^ (bkr & 7)) << 4));
            cp16(st + STG_OP + sw, Bb + (size_t)(k + bkr) * DIM + chunk * 8);
        }
        cp_commit();
    };

    issue(0); issue(1);
    const int NP = 8;
    for (int p = 0; p < NP; p++) {
        if (p + 1 < NP) cp_wait<1>(); else cp_wait<0>();
        __syncthreads();
        if (p + 2 < NP) issue(p + 2);
        uint32_t ab = sbase + (p % 3) * STG_PAIR;
        compute_ctx(ab, ab + STG_OP, m0, n0, lane, acc);
    }

    #pragma unroll
    for (int mi = 0; mi < 4; mi++)
        #pragma unroll
        for (int nj = 0; nj < 8; nj++) {
            int row = mBase + m0 + mi * 16 + (lane >> 2);
            int col = nBase + n0 + nj * 8 + (lane & 3) * 2;
            *(uint32_t*)(Cb + (size_t)row * DIM + col) = f2h2(acc[mi][nj][0], acc[mi][nj][1]);
            *(uint32_t*)(Cb + (size_t)(row + 8) * DIM + col) = f2h2(acc[mi][nj][2], acc[mi][nj][3]);
        }
}

// ---------------------------------------------------------------------------
// Kernel 4: out = tanh([Qh|Ch] . Wh^T + b) * mask  (NT, K=1024)
// ---------------------------------------------------------------------------
__global__ __launch_bounds__(128, 2) void hgemm_out(
    const __half* __restrict__ Qh, const __half* __restrict__ Ch,
    const __half* __restrict__ Wh,
    const float* __restrict__ bias, const float* __restrict__ mask,
    float* __restrict__ O)
{
    extern __shared__ uint32_t sm[];
    const int b = blockIdx.z, mBase = blockIdx.y * 128, nBase = blockIdx.x * 128;
    const __half* A0 = Qh + (size_t)b * SQ * DIM + (size_t)mBase * DIM;
    const __half* A1 = Ch + (size_t)b * SQ * DIM + (size_t)mBase * DIM;
    const __half* Bb = Wh + (size_t)nBase * DIM2;
    float* Ob = O + (size_t)b * SQ * DIM;

    const int tid = threadIdx.x, lane = tid & 31, w = tid >> 5;
    const int m0 = (w & 1) * 64, n0 = (w >> 1) * 64;
    const int lc = tid & 7, lr = tid >> 3;
    const uint32_t sbase = smem_u32(sm);

    float acc[4][8][4];
    #pragma unroll
    for (int i = 0; i < 4; i++)
        #pragma unroll
        for (int j = 0; j < 8; j++)
            #pragma unroll
            for (int qq = 0; qq < 4; qq++) acc[i][j][qq] = 0.f;

    auto issue = [&](int p) {
        uint32_t st = sbase + (p % 3) * STG_PAIR;
        const __half* Ap = (p < 8) ? A0 : A1;
        int ka = (p & 7) * BK;
        int kb = p * BK;
        #pragma unroll
        for (int i = 0; i < 8; i++) {
            int row = lr + 16 * i;
            uint32_t sw = (uint32_t)(row * 128 + ((lc ^ (row & 7)) << 4));
            cp16(st + sw, Ap + (size_t)row * DIM + ka + lc * 8);
            cp16(st + STG_OP + sw, Bb + (size_t)row * DIM2 + kb + lc * 8);
        }
        cp_commit();
    };

    issue(0); issue(1);
    const int NP = 16;
    for (int p = 0; p < NP; p++) {
        if (p + 1 < NP) cp_wait<1>(); else cp_wait<0>();
        __syncthreads();
        if (p + 2 < NP) issue(p + 2);
        uint32_t ab = sbase + (p % 3) * STG_PAIR;
        compute_fp16(ab, ab + STG_OP, m0, n0, lane, acc);
    }

    #pragma unroll
    for (int mi = 0; mi < 4; mi++)
        #pragma unroll
        for (int nj = 0; nj < 8; nj++) {
            int row = mBase + m0 + mi * 16 + (lane >> 2);
            int col = nBase + n0 + nj * 8 + (lane & 3) * 2;
            float b0 = bias[col], b1 = bias[col + 1];
            float mk0 = mask[(size_t)b * SQ + row];
            float mk1 = mask[(size_t)b * SQ + row + 8];
            *(float2*)(Ob + (size_t)row * DIM + col) =
                make_float2(tanhf(acc[mi][nj][0] + b0) * mk0,
                            tanhf(acc[mi][nj][1] + b1) * mk0);
            *(float2*)(Ob + (size_t)(row + 8) * DIM + col) =
                make_float2(tanhf(acc[mi][nj][2] + b0) * mk1,
                            tanhf(acc[mi][nj][3] + b1) * mk1);
        }
}

// ---------------------------------------------------------------------------
// support kernels
// ---------------------------------------------------------------------------
__global__ __launch_bounds__(256) void cvt_f2h(
    const float4* __restrict__ in, uint2* __restrict__ out, int n4)
{
    int i = blockIdx.x * 256 + threadIdx.x;
    if (i < n4) {
        float4 v = in[i];
        out[i] = make_uint2(f2h2(v.x, v.y), f2h2(v.z, v.w));
    }
}

// softmax over raw scores (vectorized): weights = softmax(raw * SCALE)
__global__ __launch_bounds__(128) void softmax_rows(
    float* __restrict__ S, __half* __restrict__ Ah)
{
    const int row = blockIdx.x;
    float* p = S + (size_t)row * SK;
    __half* ph = Ah + (size_t)row * SK;
    const int tid = threadIdx.x;

    float4 v = *(float4*)(p + tid * 4);
    v.x *= SCALE; v.y *= SCALE; v.z *= SCALE; v.w *= SCALE;

    __shared__ float red[4];

    float m = fmaxf(fmaxf(v.x, v.y), fmaxf(v.z, v.w));
    #pragma unroll
    for (int o = 16; o > 0; o >>= 1) m = fmaxf(m, __shfl_xor_sync(0xffffffffu, m, o));
    if ((tid & 31) == 0) red[tid >> 5] = m;
    __syncthreads();
    m = fmaxf(fmaxf(red[0], red[1]), fmaxf(red[2], red[3]));

    float4 e;
    e.x = __expf(v.x - m); e.y = __expf(v.y - m);
    e.z = __expf(v.z - m); e.w = __expf(v.w - m);

    float s = (e.x + e.y) + (e.z + e.w);
    #pragma unroll
    for (int o = 16; o > 0; o >>= 1) s += __shfl_xor_sync(0xffffffffu, s, o);
    __syncthreads();
    if ((tid & 31) == 0) red[tid >> 5] = s;
    __syncthreads();
    s = (red[0] + red[1]) + (red[2] + red[3]);

    float inv = 1.0f / s;
    e.x *= inv; e.y *= inv; e.z *= inv; e.w *= inv;
    *(float4*)(p + tid * 4) = e;
    *(uint2*)(ph + tid * 4) = make_uint2(f2h2(e.x, e.y), f2h2(e.z, e.w));
}

// ---------------------------------------------------------------------------
extern "C" void kernel_launch(void* const* d_in, const int* in_sizes, int n_in,
                              void* d_out, int out_size)
{
    const float* Q    = (const float*)d_in[0];
    const float* E    = (const float*)d_in[1];
    const float* mask = (const float*)d_in[2];
    const float* W    = (const float*)d_in[3];
    const float* bias = (const float*)d_in[4];

    float* out = (float*)d_out;
    float* out_masked  = out;
    float* out_weights = out + (size_t)BATCH * SQ * DIM;

    void *pQ, *pE, *pW, *pA, *pC;
    cudaGetSymbolAddress(&pQ, g_Qh);
    cudaGetSymbolAddress(&pE, g_Eh);
    cudaGetSymbolAddress(&pW, g_Wh);
    cudaGetSymbolAddress(&pA, g_Ah);
    cudaGetSymbolAddress(&pC, g_Ch);
    __half* Qh = (__half*)pQ;
    __half* Eh = (__half*)pE;
    __half* Wh = (__half*)pW;
    __half* Ah = (__half*)pA;
    __half* Ch = (__half*)pC;

    // 96KB dynamic smem opt-in (idempotent)
    cudaFuncSetAttribute(hgemm_scores, cudaFuncAttributeMaxDynamicSharedMemorySize, SMEM_NT);
    cudaFuncSetAttribute(hgemm_ctx, cudaFuncAttributeMaxDynamicSharedMemorySize, SMEM_NT);
    cudaFuncSetAttribute(hgemm_out, cudaFuncAttributeMaxDynamicSharedMemorySize, SMEM_NT);

    // 0) fp16 operand prep
    {
        int n4 = BATCH * SQ * DIM / 4;
        cvt_f2h<<<(n4 + 255) / 256, 256>>>((const float4*)Q, (uint2*)Qh, n4);
        cvt_f2h<<<(n4 + 255) / 256, 256>>>((const float4*)E, (uint2*)Eh, n4);
        int n4w = DIM * DIM2 / 4;
        cvt_f2h<<<(n4w + 255) / 256, 256>>>((const float4*)W, (uint2*)Wh, n4w);
    }

    dim3 grid(4, 4, BATCH);
    hgemm_scores<<<grid, 128, SMEM_NT>>>(Qh, Eh, out_weights);
    softmax_rows<<<BATCH * SQ, 128>>>(out_weights, Ah);
    hgemm_ctx<<<grid, 128, SMEM_NT>>>(Ah, Eh, Ch);
    hgemm_out<<<grid, 128, SMEM_NT>>>(Qh, Ch, Wh, bias, mask, out_masked);
}